// round 15
// baseline (speedup 1.0000x reference)
#include <cuda_runtime.h>
#include <cuda_bf16.h>
#include <cuda_fp16.h>
#include <math.h>
#include <stdint.h>

#define B_    4096
#define FEW   5
#define NN_   64
#define NSYM  100000
#define DM    256
#define DI    512
#define G1K   1024
#define XS    288    // X row stride: 256 h + 5 attn + 27 zero pad
#define YROWS (B_ * 4 + FEW * 4)   // 16404
#define YPAD  16512

// ---------------- scratch (static device globals; no allocation) -------------
__device__ float4   g_scal[NSYM];
__device__ __half   g_embh[(size_t)NSYM * 128];
__device__ float    g_u[2 * 128];
__device__ float    g_gw[2];
__device__ float    g_biasvec[128];
__device__ uint16_t g_Yhi[(size_t)YPAD * 256];
__device__ float    g_P[(size_t)YPAD * 128];
__device__ float    g_qn[(size_t)B_ * DM];
__device__ uint16_t g_qnhi[(size_t)B_ * DM];
__device__ float    g_sn[FEW * DM];
__device__ float    g_h1[FEW * DI];
__device__ float    g_z[FEW * DM];
__device__ float    g_sg[FEW * DM];
__device__ float    g_sm[DM];
__device__ uint16_t g_Wghi[128 * 256];
__device__ uint16_t g_WihNhi[1024 * 256];       // interleaved gate cols
__device__ uint16_t g_WsNhi[1024 * XS];         // interleaved gate cols
__device__ float    g_bias2[G1K];
__device__ float    g_A[(size_t)B_ * G1K];
__device__ uint16_t g_Xhi[(size_t)B_ * XS];
__device__ float    g_c[(size_t)B_ * 256];

// HW tanh: 1 MUFU op
__device__ __forceinline__ float htanh(float x) {
    float y;
    asm("tanh.approx.f32 %0, %1;" : "=f"(y) : "f"(x));
    return y;
}
__device__ __forceinline__ float hsig(float x) {
    return fmaf(htanh(0.5f * x), 0.5f, 0.5f);
}
__device__ __forceinline__ uint32_t pb2(float x, float y) {
    __nv_bfloat162 h = __floats2bfloat162_rn(x, y);
    return *(uint32_t*)&h;
}
__device__ __forceinline__ uint16_t pb1(float x) {
    __nv_bfloat16 h = __float2bfloat16(x);
    return *(uint16_t*)&h;
}
__device__ __forceinline__ float2 bf2x(uint32_t v) {
    return make_float2(__uint_as_float(v << 16), __uint_as_float(v & 0xffff0000u));
}
__device__ __forceinline__ uint32_t smem_u32(const void* p) {
    uint32_t a;
    asm("{ .reg .u64 t; cvta.to.shared.u64 t, %1; cvt.u32.u64 %0, t; }" : "=r"(a) : "l"(p));
    return a;
}
__device__ __forceinline__ void cpa16(uint32_t s, const void* g, int szd) {
    asm volatile("cp.async.cg.shared.global [%0], [%1], 16, %2;"
                 :: "r"(s), "l"(g), "r"(szd) : "memory");
}
#define CP_COMMIT() asm volatile("cp.async.commit_group;" ::: "memory")
#define CP_WAIT0()  asm volatile("cp.async.wait_group 0;" ::: "memory")
#define CP_WAIT1()  asm volatile("cp.async.wait_group 1;" ::: "memory")

__device__ __forceinline__ float warp_sum(float v) {
#pragma unroll
    for (int o = 16; o; o >>= 1) v += __shfl_down_sync(0xffffffffu, v, o);
    return v;
}

// ---------------- fused support-encoder chain (one 256-thread block) ----------
__device__ void support_chain(const float* __restrict__ p1_w, const float* __restrict__ p1_b,
                              const float* __restrict__ p2_w, const float* __restrict__ p2_b,
                              const float* __restrict__ ln_g, const float* __restrict__ ln_b,
                              const float* __restrict__ w_hh) {
    __shared__ float sred[8];
    const int t = threadIdx.x;
    // sup1: h1 = relu(sn @ p1_w^T + p1_b)
    for (int gw = t; gw < FEW * DI; gw += 256) {
        int f = gw >> 9, j = gw & 511;
        const float* sn = &g_sn[f * DM];
        const float* wr = &p1_w[j * DM];
        float s = 0.f;
#pragma unroll 8
        for (int k = 0; k < DM; k++) s += sn[k] * wr[k];
        g_h1[gw] = fmaxf(s + p1_b[j], 0.f);
    }
    __syncthreads();
    // sup2: z = h1 @ p2_w^T + p2_b + sn
    for (int gw = t; gw < FEW * DM; gw += 256) {
        int f = gw >> 8, d = gw & 255;
        const float* h1 = &g_h1[f * DI];
        const float* wr = &p2_w[d * DI];
        float s = 0.f;
#pragma unroll 8
        for (int k = 0; k < DI; k++) s += h1[k] * wr[k];
        g_z[gw] = s + p2_b[d] + g_sn[gw];
    }
    __syncthreads();
    // layernorm + mean (256 threads exactly)
    int lane = t & 31, warp = t >> 5;
    float gg = ln_g[t], bb = ln_b[t];
    float msum = 0.f;
    for (int f = 0; f < FEW; f++) {
        float z = g_z[f * DM + t];
        float v = warp_sum(z);
        if (lane == 0) sred[warp] = v;
        __syncthreads();
        if (t == 0) {
            float s = 0.f;
            for (int w = 0; w < 8; w++) s += sred[w];
            sred[0] = s * (1.f / 256.f);
        }
        __syncthreads();
        float mu = sred[0];
        __syncthreads();
        float dv = z - mu;
        float v2 = warp_sum(dv * dv);
        if (lane == 0) sred[warp] = v2;
        __syncthreads();
        if (t == 0) {
            float s = 0.f;
            for (int w = 0; w < 8; w++) s += sred[w];
            sred[0] = s * (1.f / 256.f);
        }
        __syncthreads();
        float var = sred[0];
        __syncthreads();
        float o = dv * rsqrtf(var + 1e-6f) * gg + bb;
        g_sg[f * DM + t] = o;
        msum += o;
    }
    g_sm[t] = msum * (1.f / (float)FEW);
    __syncthreads();
    // sgw: WsN cols 256..260 = sg @ whh_r^T (interleaved gate cols)
    for (int gw = t; gw < FEW * G1K; gw += 256) {
        int f = gw >> 10, n = gw & 1023;
        int src = (n & 3) * 512 + (n >> 2);
        const float* sg = &g_sg[f * DM];
        const float* wr = &w_hh[src * 512 + 256];
        float s = 0.f;
#pragma unroll 8
        for (int k = 0; k < DM; k++) s += sg[k] * wr[k];
        g_WsNhi[n * XS + 256 + f] = pb1(s);
    }
}

// ---------------- mma.sync pure-bf16 GEMM + cp.async pipeline -----------------
#define KC 32
#define SMS 40
#define BUFB 20480
#define SQ 36
#define SH 40

__device__ __forceinline__ void mma16816(float* d, const uint32_t* a,
                                         const uint32_t* b) {
    asm volatile(
        "mma.sync.aligned.m16n8k16.row.col.f32.bf16.bf16.f32 "
        "{%0,%1,%2,%3}, {%4,%5,%6,%7}, {%8,%9}, {%0,%1,%2,%3};"
        : "+f"(d[0]), "+f"(d[1]), "+f"(d[2]), "+f"(d[3])
        : "r"(a[0]), "r"(a[1]), "r"(a[2]), "r"(a[3]), "r"(b[0]), "r"(b[1]));
}

// linear grid: blocks [0, Mt*Nt) do GEMM tiles; block Mt*Nt (if present) runs support_chain.
// mode 0: plain epilogue; mode 1: C write + fused LSTM (c_old=0); mode 2: fused LSTM only
__global__ __launch_bounds__(256, 2) void gemm_tc(
    const uint16_t* __restrict__ Ahi, int lda, int M,
    const uint16_t* __restrict__ Bhi, int ldb,
    float* __restrict__ C, int ldc,
    const float* __restrict__ Cadd, const float* __restrict__ bias,
    int NC, int mode, int Mt,
    const float* p1_w, const float* p1_b, const float* p2_w, const float* p2_b,
    const float* ln_g, const float* ln_b, const float* w_hh, int Nt) {
    __shared__ __align__(16) unsigned char s_raw[47104];
    float*    st_qn = (float*)s_raw;
    float*    st_c  = (float*)(s_raw + 18432);
    uint16_t* st_h  = (uint16_t*)(s_raw + 36864);

    const int bid = blockIdx.x;
    if (bid >= Mt * Nt) {
        support_chain(p1_w, p1_b, p2_w, p2_b, ln_g, ln_b, w_hh);
        return;
    }
    const int m0 = (bid % Mt) * 128, n0 = (bid / Mt) * 128;

    const int t = threadIdx.x;
    const int w = t >> 5, lane = t & 31;
    const int g = lane >> 2, tig = lane & 3;
    const int mw = (w & 3) * 32;
    const int nw = (w >> 2) * 64;

    float acc[2][8][4];
#pragma unroll
    for (int mt = 0; mt < 2; mt++)
#pragma unroll
        for (int nt = 0; nt < 8; nt++)
#pragma unroll
            for (int e = 0; e < 4; e++) acc[mt][nt][e] = 0.f;

    const int lrow = t >> 1;
    const int lhalf = (t & 1) * 16;
    const bool mok = (m0 + lrow) < M;
    const int asz = mok ? 16 : 0;
    const size_t arow = (size_t)(m0 + lrow) * lda;
    const size_t brow = (size_t)(n0 + lrow) * ldb;
    const uint32_t sb0 = smem_u32(s_raw);
    const uint32_t soff = (uint32_t)(lrow * SMS + lhalf) * 2u;

    {
        const size_t ka = arow + lhalf;
        const size_t kb_ = brow + lhalf;
        cpa16(sb0 + soff, &Ahi[ka], asz);
        cpa16(sb0 + soff + 16, &Ahi[ka + 8], asz);
        cpa16(sb0 + 10240 + soff, &Bhi[kb_], 16);
        cpa16(sb0 + 10240 + soff + 16, &Bhi[kb_ + 8], 16);
        CP_COMMIT();
    }

    for (int c = 0; c < NC; c++) {
        if (c + 1 < NC) {
            const uint32_t sb = sb0 + (uint32_t)((c + 1) & 1) * BUFB;
            const size_t ka = arow + (c + 1) * KC + lhalf;
            const size_t kb_ = brow + (c + 1) * KC + lhalf;
            cpa16(sb + soff, &Ahi[ka], asz);
            cpa16(sb + soff + 16, &Ahi[ka + 8], asz);
            cpa16(sb + 10240 + soff, &Bhi[kb_], 16);
            cpa16(sb + 10240 + soff + 16, &Bhi[kb_ + 8], 16);
            CP_COMMIT();
            CP_WAIT1();
        } else {
            CP_WAIT0();
        }
        __syncthreads();
        const uint16_t* cA = (const uint16_t*)(s_raw + (c & 1) * BUFB);
        const uint16_t* cB = (const uint16_t*)(s_raw + (c & 1) * BUFB + 10240);
#pragma unroll
        for (int k16 = 0; k16 < 2; k16++) {
            const int kb = k16 * 16 + 2 * tig;
            uint32_t ah[2][4];
#pragma unroll
            for (int mt = 0; mt < 2; mt++) {
                int r0 = (mw + mt * 16 + g) * SMS;
                int r1 = r0 + 8 * SMS;
                ah[mt][0] = *(const uint32_t*)&cA[r0 + kb];
                ah[mt][1] = *(const uint32_t*)&cA[r1 + kb];
                ah[mt][2] = *(const uint32_t*)&cA[r0 + kb + 8];
                ah[mt][3] = *(const uint32_t*)&cA[r1 + kb + 8];
            }
#pragma unroll
            for (int nt = 0; nt < 8; nt++) {
                int rn = (nw + nt * 8 + g) * SMS;
                uint32_t bh[2];
                bh[0] = *(const uint32_t*)&cB[rn + kb];
                bh[1] = *(const uint32_t*)&cB[rn + kb + 8];
#pragma unroll
                for (int mt = 0; mt < 2; mt++) {
                    mma16816(acc[mt][nt], ah[mt], bh);
                }
            }
        }
        __syncthreads();
    }

    if (mode == 0) {
#pragma unroll
        for (int mt = 0; mt < 2; mt++) {
            int mrow0 = m0 + mw + mt * 16 + g;
#pragma unroll
            for (int half = 0; half < 2; half++) {
                int m = mrow0 + half * 8;
                if (m >= M) continue;
                size_t cro = (size_t)m * ldc;
#pragma unroll
                for (int nt = 0; nt < 8; nt++) {
                    int n = n0 + nw + nt * 8 + 2 * tig;
                    float v0 = acc[mt][nt][half * 2];
                    float v1 = acc[mt][nt][half * 2 + 1];
                    if (bias) {
                        float2 bb = *(const float2*)&bias[n];
                        v0 += bb.x; v1 += bb.y;
                    }
                    if (Cadd) {
                        float2 ca = *(const float2*)&Cadd[cro + n];
                        v0 += ca.x; v1 += ca.y;
                    }
                    *(float2*)&C[cro + n] = make_float2(v0, v1);
                }
            }
        }
    } else {
        const int pb = n0 >> 2;
        const int rr = t >> 1, sc = (t & 1) * 16;
        {
            const float* src = &g_qn[(size_t)(m0 + rr) * 256 + pb + sc];
#pragma unroll
            for (int i = 0; i < 4; i++)
                *(float4*)&st_qn[rr * SQ + sc + i * 4] = *(const float4*)&src[i * 4];
        }
        if (mode == 2) {
            const float* src = &g_c[(size_t)(m0 + rr) * 256 + pb + sc];
#pragma unroll
            for (int i = 0; i < 4; i++)
                *(float4*)&st_c[rr * SQ + sc + i * 4] = *(const float4*)&src[i * 4];
        }
        __syncthreads();
#pragma unroll
        for (int mt = 0; mt < 2; mt++) {
#pragma unroll
            for (int half = 0; half < 2; half++) {
                int mloc = mw + mt * 16 + g + half * 8;
                size_t cro = (size_t)(m0 + mloc) * ldc;
#pragma unroll
                for (int nt = 0; nt < 8; nt++) {
                    int n = n0 + nw + nt * 8 + 2 * tig;
                    float v0 = acc[mt][nt][half * 2];
                    float v1 = acc[mt][nt][half * 2 + 1];
                    if (mode == 1) {
                        float2 bb = *(const float2*)&bias[n];
                        v0 += bb.x; v1 += bb.y;
                        *(float2*)&C[cro + n] = make_float2(v0, v1);
                    } else {
                        float2 ca = *(const float2*)&Cadd[cro + n];
                        v0 += ca.x; v1 += ca.y;
                    }
                    float u0 = __shfl_xor_sync(0xffffffffu, v0, 1);
                    float u1 = __shfl_xor_sync(0xffffffffu, v1, 1);
                    if ((tig & 1) == 0) {
                        int ploc = (nw >> 2) + nt * 2 + (tig >> 1);
                        float cold = (mode == 1) ? 0.f : st_c[mloc * SQ + ploc];
                        float cn = hsig(v1) * cold + hsig(v0) * htanh(u0);
                        float hv = st_qn[mloc * SQ + ploc] + hsig(u1) * htanh(cn);
                        st_c[mloc * SQ + ploc] = cn;
                        st_h[mloc * SH + ploc] = pb1(hv);
                    }
                }
            }
        }
        __syncthreads();
        {
#pragma unroll
            for (int i = 0; i < 4; i++)
                *(float4*)&g_c[(size_t)(m0 + rr) * 256 + pb + sc + i * 4] =
                    *(const float4*)&st_c[rr * SQ + sc + i * 4];
            uint16_t* dst = &g_Xhi[(size_t)(m0 + rr) * XS + pb + sc];
#pragma unroll
            for (int i = 0; i < 2; i++)
                *(uint4*)&dst[i * 8] = *(const uint4*)&st_h[rr * SH + sc + i * 8];
        }
    }
}

// ---------------- tiny prep: gw, biasvec, folded attn vectors ------------------
__global__ void k_prep0(const float* __restrict__ gcn_w, const float* __restrict__ gcn_wb,
                        const float* __restrict__ gcn_b, const float* __restrict__ hop_gate,
                        const float* __restrict__ attn_w) {
    int t = threadIdx.x;  // 256
    if (t == 0) {
        float a = hop_gate[0], bb = hop_gate[1];
        float m = fmaxf(a, bb);
        float ea = expf(a - m), eb = expf(bb - m);
        g_gw[0] = ea / (ea + eb);
        g_gw[1] = eb / (ea + eb);
    }
    if (t < 128) {
        g_biasvec[t] = gcn_wb[t] + gcn_b[t];
        float ur = 0.f, ue = 0.f;
        for (int d = 0; d < 128; d++) {
            float aw = attn_w[d];
            ur += gcn_w[d * 256 + t] * aw;
            ue += gcn_w[d * 256 + 128 + t] * aw;
        }
        g_u[t] = ur;
        g_u[128 + t] = ue;
    }
}

// ---------------- per-symbol score scalars + fp16 table (4 symbols/warp) -------
__global__ __launch_bounds__(256) void k_scal(const float* __restrict__ emb) {
    __shared__ float su[256];
    int t = threadIdx.x;
    su[t] = g_u[t];
    __syncthreads();
    int warp = t >> 5, lane = t & 31;
    int s0 = (blockIdx.x * 8 + warp) * 4;   // NSYM = 3125*32
    float4 e[4];
#pragma unroll
    for (int i = 0; i < 4; i++)
        e[i] = *(const float4*)&emb[(size_t)(s0 + i) * 128 + lane * 4];
    float4 ur = ((const float4*)su)[lane];
    float4 ue = ((const float4*)(su + 128))[lane];
    float pr[4], pe[4];
#pragma unroll
    for (int i = 0; i < 4; i++) {
        pr[i] = e[i].x * ur.x + e[i].y * ur.y + e[i].z * ur.z + e[i].w * ur.w;
        pe[i] = e[i].x * ue.x + e[i].y * ue.y + e[i].z * ue.z + e[i].w * ue.w;
    }
#pragma unroll
    for (int o = 16; o; o >>= 1) {
#pragma unroll
        for (int i = 0; i < 4; i++) {
            pr[i] += __shfl_xor_sync(0xffffffffu, pr[i], o);
            pe[i] += __shfl_xor_sync(0xffffffffu, pe[i], o);
        }
    }
    if (lane == 0) {
#pragma unroll
        for (int i = 0; i < 4; i++)
            g_scal[s0 + i] = make_float4(pr[i], pe[i], 0.f, 0.f);
    }
#pragma unroll
    for (int i = 0; i < 4; i++) {
        __half2 h0 = __float22half2_rn(make_float2(e[i].x, e[i].y));
        __half2 h1 = __float22half2_rn(make_float2(e[i].z, e[i].w));
        uint2 pk;
        pk.x = *(uint32_t*)&h0;
        pk.y = *(uint32_t*)&h1;
        ((uint2*)g_embh)[(size_t)(s0 + i) * 32 + lane] = pk;
    }
}

// ---------------- neighbor encoder + folded weight prep ------------------------
// blocks [0, B_/4): query rows; [B_/4, B_/4+2): support rows; rest: weight prep.
__global__ __launch_bounds__(512) void k_neigh(
    const int* __restrict__ q0, const int* __restrict__ q1,
    const int* __restrict__ q2, const int* __restrict__ q3,
    const int* __restrict__ s0p, const int* __restrict__ s1p,
    const int* __restrict__ s2p, const int* __restrict__ s3p,
    const float* __restrict__ gcn_w,
    const float* __restrict__ w_ih, const float* __restrict__ w_hh,
    const float* __restrict__ b_ih, const float* __restrict__ b_hh) {
    __shared__ int4 smeta[16][64];
    const int t = threadIdx.x;
    if (blockIdx.x >= (B_ / 4 + 2)) {
        // weight prep: 2 units of 256 threads per block
        int u = (blockIdx.x - (B_ / 4 + 2)) * 2 + (t >> 8);
        int tt = t & 255;
        if (u < 128) {
            g_Wghi[u * 256 + tt] = pb1(gcn_w[u * 256 + tt]);
        } else {
            int n = u - 128;  // 0..1023, interleaved gate col
            int src = (n & 3) * 512 + (n >> 2);
            g_WihNhi[n * 256 + tt] = pb1(w_ih[src * 256 + tt]);
            g_WsNhi[n * XS + tt]   = pb1(w_hh[src * 512 + tt]);
            if (tt < (XS - 261)) g_WsNhi[n * XS + 261 + tt] = 0;
            if (tt == 0) g_bias2[n] = b_ih[src] + b_hh[src];
        }
        return;
    }
    const int w = t >> 5, lane = t & 31;
    const int g = w & 3;
    const bool is_sup = blockIdx.x >= (B_ / 4);
    int nb, rowbase;
    const int *c0, *c1, *c2, *c3;
    if (!is_sup) {
        nb = blockIdx.x * 4 + (w >> 2);
        rowbase = 0;
        c0 = q0; c1 = q1; c2 = q2; c3 = q3;
    } else {
        nb = (blockIdx.x - B_ / 4) * 4 + (w >> 2);
        if (nb >= FEW) return;
        rowbase = B_ * 4;
        c0 = s0p; c1 = s1p; c2 = s2p; c3 = s3p;
    }
    const int* cp = (g == 0) ? c0 : (g == 1) ? c1 : (g == 2) ? c2 : c3;

    int2 p0 = ((const int2*)cp)[(size_t)nb * NN_ + lane];
    int2 p1 = ((const int2*)cp)[(size_t)nb * NN_ + 32 + lane];
    float4 s0r = g_scal[p0.x], s0e = g_scal[p0.y];
    float4 s1r = g_scal[p1.x], s1e = g_scal[p1.y];
    float e0 = s0r.x + s0e.y;
    float e1 = s1r.x + s1e.y;
    float m = fmaxf(e0, e1);
#pragma unroll
    for (int o = 16; o; o >>= 1) m = fmaxf(m, __shfl_xor_sync(0xffffffffu, m, o));
    float w0 = __expf(e0 - m), w1 = __expf(e1 - m);
    float s = w0 + w1;
#pragma unroll
    for (int o = 16; o; o >>= 1) s += __shfl_xor_sync(0xffffffffu, s, o);
    float inv = __fdividef(1.f, s);

    smeta[w][lane]      = make_int4(p0.x, p0.y, __float_as_int(w0), 0);
    smeta[w][lane + 32] = make_int4(p1.x, p1.y, __float_as_int(w1), 0);
    __syncwarp();

    const uint2* e2 = (const uint2*)g_embh;
    float4 accR = make_float4(0.f, 0.f, 0.f, 0.f);
    float4 accE = make_float4(0.f, 0.f, 0.f, 0.f);
#pragma unroll 4
    for (int j = 0; j < NN_; j++) {
        int4 mt = smeta[w][j];
        float wj = __int_as_float(mt.z);
        uint2 vr = __ldg(&e2[(size_t)mt.x * 32 + lane]);
        uint2 ve = __ldg(&e2[(size_t)mt.y * 32 + lane]);
        float2 r01 = __half22float2(*(__half2*)&vr.x);
        float2 r23 = __half22float2(*(__half2*)&vr.y);
        float2 q01 = __half22float2(*(__half2*)&ve.x);
        float2 q23 = __half22float2(*(__half2*)&ve.y);
        accR.x += wj * r01.x; accR.y += wj * r01.y;
        accR.z += wj * r23.x; accR.w += wj * r23.y;
        accE.x += wj * q01.x; accE.y += wj * q01.y;
        accE.z += wj * q23.x; accE.w += wj * q23.y;
    }
    accR.x *= inv; accR.y *= inv; accR.z *= inv; accR.w *= inv;
    accE.x *= inv; accE.y *= inv; accE.z *= inv; accE.w *= inv;

    size_t yrow = (size_t)(rowbase + nb * 4 + g) * 256;
    *(uint2*)&g_Yhi[yrow + 4 * lane] =
        make_uint2(pb2(accR.x, accR.y), pb2(accR.z, accR.w));
    *(uint2*)&g_Yhi[yrow + 128 + 4 * lane] =
        make_uint2(pb2(accE.x, accE.y), pb2(accE.z, accE.w));
}

// ---------------- combine: tanh + hop-gate mix (merged q + s) ------------------
__global__ void k_mix() {
    int nb = blockIdx.x, t = threadIdx.x;  // 256
    int side = t >> 7, d = t & 127;
    if (nb < B_) {
        size_t r0 = (size_t)(nb * 4 + side * 2) * 128;
        float v = g_gw[0] * htanh(g_P[r0 + d]) + g_gw[1] * htanh(g_P[r0 + 128 + d]);
        g_qn[(size_t)nb * 256 + t] = v;
        g_qnhi[(size_t)nb * 256 + t] = pb1(v);
    } else {
        int f = nb - B_;
        size_t r0 = (size_t)(B_ * 4 + f * 4 + side * 2) * 128;
        float v = g_gw[0] * htanh(g_P[r0 + d]) + g_gw[1] * htanh(g_P[r0 + 128 + d]);
        g_sn[f * 256 + t] = v;
    }
}

// ---------------- attention softmax over support (per LSTM step) ---------------
__global__ __launch_bounds__(256) void k_attn() {
    __shared__ float ssg[FEW * 256];
    int t = threadIdx.x;
    for (int i = t; i < FEW * 256; i += 256) ssg[i] = g_sg[i];
    __syncthreads();
    int w = t >> 5, lane = t & 31;
    size_t row = (size_t)blockIdx.x * 8 + w;
    uint4 h4 = *(const uint4*)&g_Xhi[row * XS + lane * 8];
    float hv[8];
    {
        float2 a;
        a = bf2x(h4.x); hv[0] = a.x; hv[1] = a.y;
        a = bf2x(h4.y); hv[2] = a.x; hv[3] = a.y;
        a = bf2x(h4.z); hv[4] = a.x; hv[5] = a.y;
        a = bf2x(h4.w); hv[6] = a.x; hv[7] = a.y;
    }
    float s[FEW];
#pragma unroll
    for (int f = 0; f < FEW; f++) {
        float acc = 0.f;
#pragma unroll
        for (int k = 0; k < 8; k++) acc += hv[k] * ssg[f * 256 + lane * 8 + k];
#pragma unroll
        for (int o = 16; o; o >>= 1) acc += __shfl_xor_sync(0xffffffffu, acc, o);
        s[f] = acc;
    }
    float m = s[0];
#pragma unroll
    for (int f = 1; f < FEW; f++) m = fmaxf(m, s[f]);
    float sum = 0.f, e[FEW];
#pragma unroll
    for (int f = 0; f < FEW; f++) { e[f] = __expf(s[f] - m); sum += e[f]; }
    float inv = __fdividef(1.f, sum);
    if (lane < FEW) {
        g_Xhi[row * XS + 256 + lane] = pb1(e[lane] * inv);
    } else {
        g_Xhi[row * XS + 261 + (lane - FEW)] = 0;
    }
}

// ---------------- final output dot ---------------------------------------------
__global__ __launch_bounds__(256) void k_final(float* __restrict__ out) {
    __shared__ float ssm[256];
    int t = threadIdx.x;
    ssm[t] = g_sm[t];
    __syncthreads();
    int w = t >> 5, lane = t & 31;
    size_t row = (size_t)blockIdx.x * 8 + w;
    uint4 h4 = *(const uint4*)&g_Xhi[row * XS + lane * 8];
    float acc = 0.f;
    {
        float2 a;
        const float* sm = &ssm[lane * 8];
        a = bf2x(h4.x); acc += a.x * sm[0] + a.y * sm[1];
        a = bf2x(h4.y); acc += a.x * sm[2] + a.y * sm[3];
        a = bf2x(h4.z); acc += a.x * sm[4] + a.y * sm[5];
        a = bf2x(h4.w); acc += a.x * sm[6] + a.y * sm[7];
    }
#pragma unroll
    for (int o = 16; o; o >>= 1) acc += __shfl_xor_sync(0xffffffffu, acc, o);
    if (lane == 0) out[row] = acc;
}

// ---------------- host launcher ------------------------------------------------
template <typename T>
static float* symaddrf(T& sym) {
    void* p = nullptr;
    cudaGetSymbolAddress(&p, sym);
    return (float*)p;
}
template <typename T>
static uint16_t* symaddru(T& sym) {
    void* p = nullptr;
    cudaGetSymbolAddress(&p, sym);
    return (uint16_t*)p;
}

extern "C" void kernel_launch(void* const* d_in, const int* in_sizes, int n_in,
                              void* d_out, int out_size) {
    const int* q_l1 = (const int*)d_in[0];
    const int* q_l2 = (const int*)d_in[1];
    const int* q_r1 = (const int*)d_in[2];
    const int* q_r2 = (const int*)d_in[3];
    const int* s_l1 = (const int*)d_in[4];
    const int* s_l2 = (const int*)d_in[5];
    const int* s_r1 = (const int*)d_in[6];
    const int* s_r2 = (const int*)d_in[7];
    const float* emb      = (const float*)d_in[12];
    const float* gcn_w    = (const float*)d_in[13];
    const float* gcn_wb   = (const float*)d_in[14];
    const float* gcn_b    = (const float*)d_in[15];
    const float* hop_gate = (const float*)d_in[16];
    const float* attn_w   = (const float*)d_in[17];
    const float* p1_w = (const float*)d_in[19];
    const float* p1_b = (const float*)d_in[20];
    const float* p2_w = (const float*)d_in[21];
    const float* p2_b = (const float*)d_in[22];
    const float* ln_g = (const float*)d_in[23];
    const float* ln_b = (const float*)d_in[24];
    const float* w_ih = (const float*)d_in[25];
    const float* w_hh = (const float*)d_in[26];
    const float* b_ih = (const float*)d_in[27];
    const float* b_hh = (const float*)d_in[28];
    float* out = (float*)d_out;

    uint16_t* pYhi   = symaddru(g_Yhi);
    uint16_t* pWghi  = symaddru(g_Wghi);
    uint16_t* pWihhi = symaddru(g_WihNhi);
    uint16_t* pWshi  = symaddru(g_WsNhi);
    uint16_t* pQhi   = symaddru(g_qnhi);
    uint16_t* pXhi   = symaddru(g_Xhi);
    float* pP     = symaddrf(g_P);
    float* pBias2 = symaddrf(g_bias2);
    float* pBiasV = symaddrf(g_biasvec);
    float* pA     = symaddrf(g_A);

    // prep scalars (critical path for k_scal)
    k_prep0<<<1, 256>>>(gcn_w, gcn_wb, gcn_b, hop_gate, attn_w);
    k_scal<<<NSYM / 32, 256>>>(emb);

    // neighbor encoders + folded weight prep (576 extra blocks)
    k_neigh<<<B_ / 4 + 2 + 576, 512>>>(q_l1, q_l2, q_r1, q_r2,
                                       s_l1, s_l2, s_r1, s_r2,
                                       gcn_w, w_ih, w_hh, b_ih, b_hh);

    // P = Y @ gcn_w^T + biasvec   [16404,256]@[256,128]
    gemm_tc<<<129, 256>>>(
        pYhi, 256, YROWS, pWghi, 256, pP, 128, nullptr, pBiasV, 8, 0, 129,
        nullptr, nullptr, nullptr, nullptr, nullptr, nullptr, nullptr, 1);

    // tanh + hop-gate mix (merged q + s)
    k_mix<<<B_ + FEW, 256>>>();

    // A-GEMM (mode 1) + fused support-encoder chain as extra block
    gemm_tc<<<257, 256>>>(
        pQhi, 256, B_, pWihhi, 256, pA, G1K, nullptr, pBias2, 8, 1, 32,
        p1_w, p1_b, p2_w, p2_b, ln_g, ln_b, w_hh, 8);
    k_attn<<<B_ / 8, 256>>>();

    // steps 2..4: gates = A + X @ WsN^T, fused cell (mode 2)
    for (int s = 2; s <= 4; s++) {
        gemm_tc<<<256, 256>>>(
            pXhi, XS, B_, pWshi, XS, nullptr, G1K, pA, nullptr, 9, 2, 32,
            nullptr, nullptr, nullptr, nullptr, nullptr, nullptr, nullptr, 8);
        if (s < 4)
            k_attn<<<B_ / 8, 256>>>();
        else
            k_final<<<B_ / 8, 256>>>(out);
    }
}

// round 16
// speedup vs baseline: 7.4860x; 7.4860x over previous
#include <cuda_runtime.h>
#include <cuda_bf16.h>
#include <cuda_fp16.h>
#include <math.h>
#include <stdint.h>

#define B_    4096
#define FEW   5
#define NN_   64
#define NSYM  100000
#define DM    256
#define DI    512
#define G1K   1024
#define XS    288    // X row stride: 256 h + 5 attn + 27 zero pad
#define YROWS (B_ * 4 + FEW * 4)   // 16404
#define YPAD  16512

// ---------------- scratch (static device globals; no allocation) -------------
__device__ float4   g_scal[NSYM];
__device__ __half   g_embh[(size_t)NSYM * 128];
__device__ float    g_u[2 * 128];
__device__ float    g_gw[2];
__device__ float    g_biasvec[128];
__device__ uint16_t g_Yhi[(size_t)YPAD * 256];
__device__ float    g_P[(size_t)YPAD * 128];
__device__ float    g_qn[(size_t)B_ * DM];
__device__ uint16_t g_qnhi[(size_t)B_ * DM];
__device__ float    g_sn[FEW * DM];
__device__ float    g_h1[FEW * DI];
__device__ float    g_z[FEW * DM];
__device__ float    g_sg[FEW * DM];
__device__ float    g_sm[DM];
__device__ uint16_t g_Wghi[128 * 256];
__device__ uint16_t g_WihNhi[1024 * 256];       // interleaved gate cols
__device__ uint16_t g_WsNhi[1024 * XS];         // interleaved gate cols
__device__ float    g_bias2[G1K];
__device__ float    g_A[(size_t)B_ * G1K];
__device__ uint16_t g_Xhi[(size_t)B_ * XS];
__device__ float    g_c[(size_t)B_ * 256];

// HW tanh: 1 MUFU op
__device__ __forceinline__ float htanh(float x) {
    float y;
    asm("tanh.approx.f32 %0, %1;" : "=f"(y) : "f"(x));
    return y;
}
__device__ __forceinline__ float hsig(float x) {
    return fmaf(htanh(0.5f * x), 0.5f, 0.5f);
}
__device__ __forceinline__ uint32_t pb2(float x, float y) {
    __nv_bfloat162 h = __floats2bfloat162_rn(x, y);
    return *(uint32_t*)&h;
}
__device__ __forceinline__ uint16_t pb1(float x) {
    __nv_bfloat16 h = __float2bfloat16(x);
    return *(uint16_t*)&h;
}
__device__ __forceinline__ float2 bf2x(uint32_t v) {
    return make_float2(__uint_as_float(v << 16), __uint_as_float(v & 0xffff0000u));
}
__device__ __forceinline__ uint32_t smem_u32(const void* p) {
    uint32_t a;
    asm("{ .reg .u64 t; cvta.to.shared.u64 t, %1; cvt.u32.u64 %0, t; }" : "=r"(a) : "l"(p));
    return a;
}
__device__ __forceinline__ void cpa16(uint32_t s, const void* g, int szd) {
    asm volatile("cp.async.cg.shared.global [%0], [%1], 16, %2;"
                 :: "r"(s), "l"(g), "r"(szd) : "memory");
}
#define CP_COMMIT() asm volatile("cp.async.commit_group;" ::: "memory")
#define CP_WAIT0()  asm volatile("cp.async.wait_group 0;" ::: "memory")
#define CP_WAIT1()  asm volatile("cp.async.wait_group 1;" ::: "memory")

__device__ __forceinline__ float warp_sum(float v) {
#pragma unroll
    for (int o = 16; o; o >>= 1) v += __shfl_down_sync(0xffffffffu, v, o);
    return v;
}

// ---------------- mma.sync pure-bf16 GEMM + cp.async pipeline -----------------
#define KC 32
#define SMS 40
#define BUFB 20480
#define SQ 36
#define SH 40

__device__ __forceinline__ void mma16816(float* d, const uint32_t* a,
                                         const uint32_t* b) {
    asm volatile(
        "mma.sync.aligned.m16n8k16.row.col.f32.bf16.bf16.f32 "
        "{%0,%1,%2,%3}, {%4,%5,%6,%7}, {%8,%9}, {%0,%1,%2,%3};"
        : "+f"(d[0]), "+f"(d[1]), "+f"(d[2]), "+f"(d[3])
        : "r"(a[0]), "r"(a[1]), "r"(a[2]), "r"(a[3]), "r"(b[0]), "r"(b[1]));
}

// mode 0: plain epilogue; mode 1: C write + fused LSTM (c_old=0); mode 2: fused LSTM only
__global__ __launch_bounds__(256, 2) void gemm_tc(
    const uint16_t* __restrict__ Ahi, int lda, int M,
    const uint16_t* __restrict__ Bhi, int ldb,
    float* __restrict__ C, int ldc,
    const float* __restrict__ Cadd, const float* __restrict__ bias,
    int NC, int mode) {
    __shared__ __align__(16) unsigned char s_raw[47104];
    float*    st_qn = (float*)s_raw;
    float*    st_c  = (float*)(s_raw + 18432);
    uint16_t* st_h  = (uint16_t*)(s_raw + 36864);

    const int t = threadIdx.x;
    const int w = t >> 5, lane = t & 31;
    const int g = lane >> 2, tig = lane & 3;
    const int m0 = blockIdx.x * 128, n0 = blockIdx.y * 128;
    const int mw = (w & 3) * 32;
    const int nw = (w >> 2) * 64;

    float acc[2][8][4];
#pragma unroll
    for (int mt = 0; mt < 2; mt++)
#pragma unroll
        for (int nt = 0; nt < 8; nt++)
#pragma unroll
            for (int e = 0; e < 4; e++) acc[mt][nt][e] = 0.f;

    const int lrow = t >> 1;
    const int lhalf = (t & 1) * 16;
    const bool mok = (m0 + lrow) < M;
    const int asz = mok ? 16 : 0;
    const size_t arow = (size_t)(m0 + lrow) * lda;
    const size_t brow = (size_t)(n0 + lrow) * ldb;
    const uint32_t sb0 = smem_u32(s_raw);
    const uint32_t soff = (uint32_t)(lrow * SMS + lhalf) * 2u;

    {
        const size_t ka = arow + lhalf;
        const size_t kb_ = brow + lhalf;
        cpa16(sb0 + soff, &Ahi[ka], asz);
        cpa16(sb0 + soff + 16, &Ahi[ka + 8], asz);
        cpa16(sb0 + 10240 + soff, &Bhi[kb_], 16);
        cpa16(sb0 + 10240 + soff + 16, &Bhi[kb_ + 8], 16);
        CP_COMMIT();
    }

    for (int c = 0; c < NC; c++) {
        if (c + 1 < NC) {
            const uint32_t sb = sb0 + (uint32_t)((c + 1) & 1) * BUFB;
            const size_t ka = arow + (c + 1) * KC + lhalf;
            const size_t kb_ = brow + (c + 1) * KC + lhalf;
            cpa16(sb + soff, &Ahi[ka], asz);
            cpa16(sb + soff + 16, &Ahi[ka + 8], asz);
            cpa16(sb + 10240 + soff, &Bhi[kb_], 16);
            cpa16(sb + 10240 + soff + 16, &Bhi[kb_ + 8], 16);
            CP_COMMIT();
            CP_WAIT1();
        } else {
            CP_WAIT0();
        }
        __syncthreads();
        const uint16_t* cA = (const uint16_t*)(s_raw + (c & 1) * BUFB);
        const uint16_t* cB = (const uint16_t*)(s_raw + (c & 1) * BUFB + 10240);
#pragma unroll
        for (int k16 = 0; k16 < 2; k16++) {
            const int kb = k16 * 16 + 2 * tig;
            uint32_t ah[2][4];
#pragma unroll
            for (int mt = 0; mt < 2; mt++) {
                int r0 = (mw + mt * 16 + g) * SMS;
                int r1 = r0 + 8 * SMS;
                ah[mt][0] = *(const uint32_t*)&cA[r0 + kb];
                ah[mt][1] = *(const uint32_t*)&cA[r1 + kb];
                ah[mt][2] = *(const uint32_t*)&cA[r0 + kb + 8];
                ah[mt][3] = *(const uint32_t*)&cA[r1 + kb + 8];
            }
#pragma unroll
            for (int nt = 0; nt < 8; nt++) {
                int rn = (nw + nt * 8 + g) * SMS;
                uint32_t bh[2];
                bh[0] = *(const uint32_t*)&cB[rn + kb];
                bh[1] = *(const uint32_t*)&cB[rn + kb + 8];
#pragma unroll
                for (int mt = 0; mt < 2; mt++) {
                    mma16816(acc[mt][nt], ah[mt], bh);
                }
            }
        }
        __syncthreads();
    }

    if (mode == 0) {
#pragma unroll
        for (int mt = 0; mt < 2; mt++) {
            int mrow0 = m0 + mw + mt * 16 + g;
#pragma unroll
            for (int half = 0; half < 2; half++) {
                int m = mrow0 + half * 8;
                if (m >= M) continue;
                size_t cro = (size_t)m * ldc;
#pragma unroll
                for (int nt = 0; nt < 8; nt++) {
                    int n = n0 + nw + nt * 8 + 2 * tig;
                    float v0 = acc[mt][nt][half * 2];
                    float v1 = acc[mt][nt][half * 2 + 1];
                    if (bias) {
                        float2 bb = *(const float2*)&bias[n];
                        v0 += bb.x; v1 += bb.y;
                    }
                    if (Cadd) {
                        float2 ca = *(const float2*)&Cadd[cro + n];
                        v0 += ca.x; v1 += ca.y;
                    }
                    *(float2*)&C[cro + n] = make_float2(v0, v1);
                }
            }
        }
    } else {
        const int pb = n0 >> 2;
        const int rr = t >> 1, sc = (t & 1) * 16;
        {
            const float* src = &g_qn[(size_t)(m0 + rr) * 256 + pb + sc];
#pragma unroll
            for (int i = 0; i < 4; i++)
                *(float4*)&st_qn[rr * SQ + sc + i * 4] = *(const float4*)&src[i * 4];
        }
        if (mode == 2) {
            const float* src = &g_c[(size_t)(m0 + rr) * 256 + pb + sc];
#pragma unroll
            for (int i = 0; i < 4; i++)
                *(float4*)&st_c[rr * SQ + sc + i * 4] = *(const float4*)&src[i * 4];
        }
        __syncthreads();
#pragma unroll
        for (int mt = 0; mt < 2; mt++) {
#pragma unroll
            for (int half = 0; half < 2; half++) {
                int mloc = mw + mt * 16 + g + half * 8;
                size_t cro = (size_t)(m0 + mloc) * ldc;
#pragma unroll
                for (int nt = 0; nt < 8; nt++) {
                    int n = n0 + nw + nt * 8 + 2 * tig;
                    float v0 = acc[mt][nt][half * 2];
                    float v1 = acc[mt][nt][half * 2 + 1];
                    if (mode == 1) {
                        float2 bb = *(const float2*)&bias[n];
                        v0 += bb.x; v1 += bb.y;
                        *(float2*)&C[cro + n] = make_float2(v0, v1);
                    } else {
                        float2 ca = *(const float2*)&Cadd[cro + n];
                        v0 += ca.x; v1 += ca.y;
                    }
                    float u0 = __shfl_xor_sync(0xffffffffu, v0, 1);
                    float u1 = __shfl_xor_sync(0xffffffffu, v1, 1);
                    if ((tig & 1) == 0) {
                        int ploc = (nw >> 2) + nt * 2 + (tig >> 1);
                        float cold = (mode == 1) ? 0.f : st_c[mloc * SQ + ploc];
                        float cn = hsig(v1) * cold + hsig(v0) * htanh(u0);
                        float hv = st_qn[mloc * SQ + ploc] + hsig(u1) * htanh(cn);
                        st_c[mloc * SQ + ploc] = cn;
                        st_h[mloc * SH + ploc] = pb1(hv);
                    }
                }
            }
        }
        __syncthreads();
        {
#pragma unroll
            for (int i = 0; i < 4; i++)
                *(float4*)&g_c[(size_t)(m0 + rr) * 256 + pb + sc + i * 4] =
                    *(const float4*)&st_c[rr * SQ + sc + i * 4];
            uint16_t* dst = &g_Xhi[(size_t)(m0 + rr) * XS + pb + sc];
#pragma unroll
            for (int i = 0; i < 2; i++)
                *(uint4*)&dst[i * 8] = *(const uint4*)&st_h[rr * SH + sc + i * 8];
        }
    }
}

// ---------------- tiny prep: gw, biasvec, folded attn vectors ------------------
__global__ void k_prep0(const float* __restrict__ gcn_w, const float* __restrict__ gcn_wb,
                        const float* __restrict__ gcn_b, const float* __restrict__ hop_gate,
                        const float* __restrict__ attn_w) {
    int t = threadIdx.x;  // 256
    if (t == 0) {
        float a = hop_gate[0], bb = hop_gate[1];
        float m = fmaxf(a, bb);
        float ea = expf(a - m), eb = expf(bb - m);
        g_gw[0] = ea / (ea + eb);
        g_gw[1] = eb / (ea + eb);
    }
    if (t < 128) {
        g_biasvec[t] = gcn_wb[t] + gcn_b[t];
        float ur = 0.f, ue = 0.f;
        for (int d = 0; d < 128; d++) {
            float aw = attn_w[d];
            ur += gcn_w[d * 256 + t] * aw;
            ue += gcn_w[d * 256 + 128 + t] * aw;
        }
        g_u[t] = ur;
        g_u[128 + t] = ue;
    }
}

// ---------------- per-symbol score scalars + fp16 table (4 symbols/warp) -------
__global__ __launch_bounds__(256) void k_scal(const float* __restrict__ emb) {
    __shared__ float su[256];
    int t = threadIdx.x;
    su[t] = g_u[t];
    __syncthreads();
    int warp = t >> 5, lane = t & 31;
    int s0 = (blockIdx.x * 8 + warp) * 4;   // NSYM = 3125*32
    float4 e[4];
#pragma unroll
    for (int i = 0; i < 4; i++)
        e[i] = *(const float4*)&emb[(size_t)(s0 + i) * 128 + lane * 4];
    float4 ur = ((const float4*)su)[lane];
    float4 ue = ((const float4*)(su + 128))[lane];
    float pr[4], pe[4];
#pragma unroll
    for (int i = 0; i < 4; i++) {
        pr[i] = e[i].x * ur.x + e[i].y * ur.y + e[i].z * ur.z + e[i].w * ur.w;
        pe[i] = e[i].x * ue.x + e[i].y * ue.y + e[i].z * ue.z + e[i].w * ue.w;
    }
#pragma unroll
    for (int o = 16; o; o >>= 1) {
#pragma unroll
        for (int i = 0; i < 4; i++) {
            pr[i] += __shfl_xor_sync(0xffffffffu, pr[i], o);
            pe[i] += __shfl_xor_sync(0xffffffffu, pe[i], o);
        }
    }
    if (lane == 0) {
#pragma unroll
        for (int i = 0; i < 4; i++)
            g_scal[s0 + i] = make_float4(pr[i], pe[i], 0.f, 0.f);
    }
#pragma unroll
    for (int i = 0; i < 4; i++) {
        __half2 h0 = __float22half2_rn(make_float2(e[i].x, e[i].y));
        __half2 h1 = __float22half2_rn(make_float2(e[i].z, e[i].w));
        uint2 pk;
        pk.x = *(uint32_t*)&h0;
        pk.y = *(uint32_t*)&h1;
        ((uint2*)g_embh)[(size_t)(s0 + i) * 32 + lane] = pk;
    }
}

// ---------------- neighbor encoder + folded weight prep ------------------------
// blocks [0, B_/4): query rows; [B_/4, B_/4+2): support rows; rest: weight prep.
__global__ __launch_bounds__(512) void k_neigh(
    const int* __restrict__ q0, const int* __restrict__ q1,
    const int* __restrict__ q2, const int* __restrict__ q3,
    const int* __restrict__ s0p, const int* __restrict__ s1p,
    const int* __restrict__ s2p, const int* __restrict__ s3p,
    const float* __restrict__ gcn_w,
    const float* __restrict__ w_ih, const float* __restrict__ w_hh,
    const float* __restrict__ b_ih, const float* __restrict__ b_hh) {
    __shared__ int4 smeta[16][64];
    const int t = threadIdx.x;
    if (blockIdx.x >= (B_ / 4 + 2)) {
        // weight prep: 2 units of 256 threads per block (coalesced row copies)
        int u = (blockIdx.x - (B_ / 4 + 2)) * 2 + (t >> 8);
        int tt = t & 255;
        if (u < 128) {
            g_Wghi[u * 256 + tt] = pb1(gcn_w[u * 256 + tt]);
        } else {
            int n = u - 128;  // 0..1023, interleaved gate col
            int src = (n & 3) * 512 + (n >> 2);
            g_WihNhi[n * 256 + tt] = pb1(w_ih[src * 256 + tt]);
            g_WsNhi[n * XS + tt]   = pb1(w_hh[src * 512 + tt]);
            if (tt < (XS - 261)) g_WsNhi[n * XS + 261 + tt] = 0;
            if (tt == 0) g_bias2[n] = b_ih[src] + b_hh[src];
        }
        return;
    }
    const int w = t >> 5, lane = t & 31;
    const int g = w & 3;
    const bool is_sup = blockIdx.x >= (B_ / 4);
    int nb, rowbase;
    const int *c0, *c1, *c2, *c3;
    if (!is_sup) {
        nb = blockIdx.x * 4 + (w >> 2);
        rowbase = 0;
        c0 = q0; c1 = q1; c2 = q2; c3 = q3;
    } else {
        nb = (blockIdx.x - B_ / 4) * 4 + (w >> 2);
        if (nb >= FEW) return;
        rowbase = B_ * 4;
        c0 = s0p; c1 = s1p; c2 = s2p; c3 = s3p;
    }
    const int* cp = (g == 0) ? c0 : (g == 1) ? c1 : (g == 2) ? c2 : c3;

    int2 p0 = ((const int2*)cp)[(size_t)nb * NN_ + lane];
    int2 p1 = ((const int2*)cp)[(size_t)nb * NN_ + 32 + lane];
    float4 s0r = g_scal[p0.x], s0e = g_scal[p0.y];
    float4 s1r = g_scal[p1.x], s1e = g_scal[p1.y];
    float e0 = s0r.x + s0e.y;
    float e1 = s1r.x + s1e.y;
    float m = fmaxf(e0, e1);
#pragma unroll
    for (int o = 16; o; o >>= 1) m = fmaxf(m, __shfl_xor_sync(0xffffffffu, m, o));
    float w0 = __expf(e0 - m), w1 = __expf(e1 - m);
    float s = w0 + w1;
#pragma unroll
    for (int o = 16; o; o >>= 1) s += __shfl_xor_sync(0xffffffffu, s, o);
    float inv = __fdividef(1.f, s);

    smeta[w][lane]      = make_int4(p0.x, p0.y, __float_as_int(w0), 0);
    smeta[w][lane + 32] = make_int4(p1.x, p1.y, __float_as_int(w1), 0);
    __syncwarp();

    const uint2* e2 = (const uint2*)g_embh;
    float4 accR = make_float4(0.f, 0.f, 0.f, 0.f);
    float4 accE = make_float4(0.f, 0.f, 0.f, 0.f);
#pragma unroll 4
    for (int j = 0; j < NN_; j++) {
        int4 mt = smeta[w][j];
        float wj = __int_as_float(mt.z);
        uint2 vr = __ldg(&e2[(size_t)mt.x * 32 + lane]);
        uint2 ve = __ldg(&e2[(size_t)mt.y * 32 + lane]);
        float2 r01 = __half22float2(*(__half2*)&vr.x);
        float2 r23 = __half22float2(*(__half2*)&vr.y);
        float2 q01 = __half22float2(*(__half2*)&ve.x);
        float2 q23 = __half22float2(*(__half2*)&ve.y);
        accR.x += wj * r01.x; accR.y += wj * r01.y;
        accR.z += wj * r23.x; accR.w += wj * r23.y;
        accE.x += wj * q01.x; accE.y += wj * q01.y;
        accE.z += wj * q23.x; accE.w += wj * q23.y;
    }
    accR.x *= inv; accR.y *= inv; accR.z *= inv; accR.w *= inv;
    accE.x *= inv; accE.y *= inv; accE.z *= inv; accE.w *= inv;

    size_t yrow = (size_t)(rowbase + nb * 4 + g) * 256;
    *(uint2*)&g_Yhi[yrow + 4 * lane] =
        make_uint2(pb2(accR.x, accR.y), pb2(accR.z, accR.w));
    *(uint2*)&g_Yhi[yrow + 128 + 4 * lane] =
        make_uint2(pb2(accE.x, accE.y), pb2(accE.z, accE.w));
}

// ---------------- combine: tanh + hop-gate mix (merged q + s) ------------------
__global__ void k_mix() {
    int nb = blockIdx.x, t = threadIdx.x;  // 256
    int side = t >> 7, d = t & 127;
    if (nb < B_) {
        size_t r0 = (size_t)(nb * 4 + side * 2) * 128;
        float v = g_gw[0] * htanh(g_P[r0 + d]) + g_gw[1] * htanh(g_P[r0 + 128 + d]);
        g_qn[(size_t)nb * 256 + t] = v;
        g_qnhi[(size_t)nb * 256 + t] = pb1(v);
    } else {
        int f = nb - B_;
        size_t r0 = (size_t)(B_ * 4 + f * 4 + side * 2) * 128;
        float v = g_gw[0] * htanh(g_P[r0 + d]) + g_gw[1] * htanh(g_P[r0 + 128 + d]);
        g_sn[f * 256 + t] = v;
    }
}

// ---------------- support encoder chain (separate, parallel kernels) -----------
__global__ void k_sup1(const float* __restrict__ p1_w, const float* __restrict__ p1_b) {
    int warp = threadIdx.x >> 5, lane = threadIdx.x & 31;
    int gw = blockIdx.x * 8 + warp;
    if (gw >= FEW * DI) return;
    int f = gw / DI, j = gw - f * DI;
    float s = 0.f;
#pragma unroll
    for (int i = 0; i < 8; i++) {
        int k = lane + i * 32;
        s += g_sn[f * DM + k] * p1_w[j * DM + k];
    }
    s = warp_sum(s);
    if (lane == 0) g_h1[f * DI + j] = fmaxf(s + p1_b[j], 0.f);
}

__global__ void k_sup2(const float* __restrict__ p2_w, const float* __restrict__ p2_b) {
    int warp = threadIdx.x >> 5, lane = threadIdx.x & 31;
    int gw = blockIdx.x * 8 + warp;
    if (gw >= FEW * DM) return;
    int f = gw / DM, d = gw - f * DM;
    float s = 0.f;
#pragma unroll
    for (int i = 0; i < 16; i++) {
        int k = lane + i * 32;
        s += g_h1[f * DI + k] * p2_w[d * DI + k];
    }
    s = warp_sum(s);
    if (lane == 0) g_z[f * DM + d] = s + p2_b[d] + g_sn[f * DM + d];
}

__global__ void k_lnmean(const float* __restrict__ ln_g, const float* __restrict__ ln_b) {
    __shared__ float sred[8];
    int t = threadIdx.x;
    int lane = t & 31, warp = t >> 5;
    float gg = ln_g[t], bb = ln_b[t];
    float msum = 0.f;
    for (int f = 0; f < FEW; f++) {
        float z = g_z[f * DM + t];
        float v = warp_sum(z);
        if (lane == 0) sred[warp] = v;
        __syncthreads();
        if (t == 0) {
            float s = 0.f;
            for (int w = 0; w < 8; w++) s += sred[w];
            sred[0] = s * (1.f / 256.f);
        }
        __syncthreads();
        float mu = sred[0];
        __syncthreads();
        float dv = z - mu;
        float v2 = warp_sum(dv * dv);
        if (lane == 0) sred[warp] = v2;
        __syncthreads();
        if (t == 0) {
            float s = 0.f;
            for (int w = 0; w < 8; w++) s += sred[w];
            sred[0] = s * (1.f / 256.f);
        }
        __syncthreads();
        float var = sred[0];
        __syncthreads();
        float o = dv * rsqrtf(var + 1e-6f) * gg + bb;
        g_sg[f * DM + t] = o;
        msum += o;
    }
    g_sm[t] = msum * (1.f / (float)FEW);
}

__global__ void k_sgw(const float* __restrict__ w_hh) {
    int warp = threadIdx.x >> 5, lane = threadIdx.x & 31;
    int gw = blockIdx.x * 8 + warp;
    if (gw >= FEW * G1K) return;
    int f = gw / G1K, n = gw - f * G1K;
    int src = (n & 3) * 512 + (n >> 2);   // interleaved gate col
    float s = 0.f;
#pragma unroll
    for (int i = 0; i < 8; i++) {
        int k = lane + i * 32;
        s += g_sg[f * DM + k] * w_hh[src * 512 + 256 + k];
    }
    s = warp_sum(s);
    if (lane == 0) g_WsNhi[n * XS + 256 + f] = pb1(s);
}

// ---------------- attention softmax over support (per LSTM step) ---------------
__global__ __launch_bounds__(256) void k_attn() {
    __shared__ float ssg[FEW * 256];
    int t = threadIdx.x;
    for (int i = t; i < FEW * 256; i += 256) ssg[i] = g_sg[i];
    __syncthreads();
    int w = t >> 5, lane = t & 31;
    size_t row = (size_t)blockIdx.x * 8 + w;
    uint4 h4 = *(const uint4*)&g_Xhi[row * XS + lane * 8];
    float hv[8];
    {
        float2 a;
        a = bf2x(h4.x); hv[0] = a.x; hv[1] = a.y;
        a = bf2x(h4.y); hv[2] = a.x; hv[3] = a.y;
        a = bf2x(h4.z); hv[4] = a.x; hv[5] = a.y;
        a = bf2x(h4.w); hv[6] = a.x; hv[7] = a.y;
    }
    float s[FEW];
#pragma unroll
    for (int f = 0; f < FEW; f++) {
        float acc = 0.f;
#pragma unroll
        for (int k = 0; k < 8; k++) acc += hv[k] * ssg[f * 256 + lane * 8 + k];
#pragma unroll
        for (int o = 16; o; o >>= 1) acc += __shfl_xor_sync(0xffffffffu, acc, o);
        s[f] = acc;
    }
    float m = s[0];
#pragma unroll
    for (int f = 1; f < FEW; f++) m = fmaxf(m, s[f]);
    float sum = 0.f, e[FEW];
#pragma unroll
    for (int f = 0; f < FEW; f++) { e[f] = __expf(s[f] - m); sum += e[f]; }
    float inv = __fdividef(1.f, sum);
    if (lane < FEW) {
        g_Xhi[row * XS + 256 + lane] = pb1(e[lane] * inv);
    } else {
        g_Xhi[row * XS + 261 + (lane - FEW)] = 0;
    }
}

// ---------------- final output dot ---------------------------------------------
__global__ __launch_bounds__(256) void k_final(float* __restrict__ out) {
    __shared__ float ssm[256];
    int t = threadIdx.x;
    ssm[t] = g_sm[t];
    __syncthreads();
    int w = t >> 5, lane = t & 31;
    size_t row = (size_t)blockIdx.x * 8 + w;
    uint4 h4 = *(const uint4*)&g_Xhi[row * XS + lane * 8];
    float acc = 0.f;
    {
        float2 a;
        const float* sm = &ssm[lane * 8];
        a = bf2x(h4.x); acc += a.x * sm[0] + a.y * sm[1];
        a = bf2x(h4.y); acc += a.x * sm[2] + a.y * sm[3];
        a = bf2x(h4.z); acc += a.x * sm[4] + a.y * sm[5];
        a = bf2x(h4.w); acc += a.x * sm[6] + a.y * sm[7];
    }
#pragma unroll
    for (int o = 16; o; o >>= 1) acc += __shfl_xor_sync(0xffffffffu, acc, o);
    if (lane == 0) out[row] = acc;
}

// ---------------- host launcher ------------------------------------------------
template <typename T>
static float* symaddrf(T& sym) {
    void* p = nullptr;
    cudaGetSymbolAddress(&p, sym);
    return (float*)p;
}
template <typename T>
static uint16_t* symaddru(T& sym) {
    void* p = nullptr;
    cudaGetSymbolAddress(&p, sym);
    return (uint16_t*)p;
}

extern "C" void kernel_launch(void* const* d_in, const int* in_sizes, int n_in,
                              void* d_out, int out_size) {
    const int* q_l1 = (const int*)d_in[0];
    const int* q_l2 = (const int*)d_in[1];
    const int* q_r1 = (const int*)d_in[2];
    const int* q_r2 = (const int*)d_in[3];
    const int* s_l1 = (const int*)d_in[4];
    const int* s_l2 = (const int*)d_in[5];
    const int* s_r1 = (const int*)d_in[6];
    const int* s_r2 = (const int*)d_in[7];
    const float* emb      = (const float*)d_in[12];
    const float* gcn_w    = (const float*)d_in[13];
    const float* gcn_wb   = (const float*)d_in[14];
    const float* gcn_b    = (const float*)d_in[15];
    const float* hop_gate = (const float*)d_in[16];
    const float* attn_w   = (const float*)d_in[17];
    const float* p1_w = (const float*)d_in[19];
    const float* p1_b = (const float*)d_in[20];
    const float* p2_w = (const float*)d_in[21];
    const float* p2_b = (const float*)d_in[22];
    const float* ln_g = (const float*)d_in[23];
    const float* ln_b = (const float*)d_in[24];
    const float* w_ih = (const float*)d_in[25];
    const float* w_hh = (const float*)d_in[26];
    const float* b_ih = (const float*)d_in[27];
    const float* b_hh = (const float*)d_in[28];
    float* out = (float*)d_out;

    uint16_t* pYhi   = symaddru(g_Yhi);
    uint16_t* pWghi  = symaddru(g_Wghi);
    uint16_t* pWihhi = symaddru(g_WihNhi);
    uint16_t* pWshi  = symaddru(g_WsNhi);
    uint16_t* pQhi   = symaddru(g_qnhi);
    uint16_t* pXhi   = symaddru(g_Xhi);
    float* pP     = symaddrf(g_P);
    float* pBias2 = symaddrf(g_bias2);
    float* pBiasV = symaddrf(g_biasvec);
    float* pA     = symaddrf(g_A);

    // prep scalars
    k_prep0<<<1, 256>>>(gcn_w, gcn_wb, gcn_b, hop_gate, attn_w);
    k_scal<<<NSYM / 32, 256>>>(emb);

    // neighbor encoders + folded weight prep (576 extra parallel blocks)
    k_neigh<<<B_ / 4 + 2 + 576, 512>>>(q_l1, q_l2, q_r1, q_r2,
                                       s_l1, s_l2, s_r1, s_r2,
                                       gcn_w, w_ih, w_hh, b_ih, b_hh);

    // P = Y @ gcn_w^T + biasvec   [16404,256]@[256,128]
    gemm_tc<<<dim3((YROWS + 127) / 128, 1), 256>>>(
        pYhi, 256, YROWS, pWghi, 256, pP, 128, nullptr, pBiasV, 8, 0);

    // tanh + hop-gate mix (merged q + s)
    k_mix<<<B_ + FEW, 256>>>();

    // support encoder (parallel, coalesced)
    k_sup1<<<(FEW * DI) / 8, 256>>>(p1_w, p1_b);
    k_sup2<<<(FEW * DM) / 8, 256>>>(p2_w, p2_b);
    k_lnmean<<<1, 256>>>(ln_g, ln_b);
    k_sgw<<<(FEW * G1K + 7) / 8, 256>>>(w_hh);

    // A-GEMM (mode 1): fused step-1 LSTM cell
    gemm_tc<<<dim3(B_ / 128, G1K / 128), 256>>>(
        pQhi, 256, B_, pWihhi, 256, pA, G1K, nullptr, pBias2, 8, 1);
    k_attn<<<B_ / 8, 256>>>();

    // steps 2..4: gates = A + X @ WsN^T, fused cell (mode 2)
    for (int s = 2; s <= 4; s++) {
        gemm_tc<<<dim3(B_ / 128, G1K / 128), 256>>>(
            pXhi, XS, B_, pWshi, XS, nullptr, G1K, pA, nullptr, 9, 2);
        if (s < 4)
            k_attn<<<B_ / 8, 256>>>();
        else
            k_final<<<B_ / 8, 256>>>(out);
    }
}

// round 17
// speedup vs baseline: 7.7098x; 1.0299x over previous
#include <cuda_runtime.h>
#include <cuda_bf16.h>
#include <cuda_fp16.h>
#include <math.h>
#include <stdint.h>

#define B_    4096
#define FEW   5
#define NN_   64
#define NSYM  100000
#define DM    256
#define DI    512
#define G1K   1024
#define XS    288    // X row stride: 256 h + 5 attn + 27 zero pad
#define YROWS (B_ * 4 + FEW * 4)   // 16404
#define YPAD  16512

// ---------------- scratch (static device globals; no allocation) -------------
__device__ float4   g_scal[NSYM];
__device__ __half   g_embh[(size_t)NSYM * 128];
__device__ float    g_u[2 * 128];
__device__ float    g_gw[2];
__device__ float    g_biasvec[128];
__device__ uint16_t g_Yhi[(size_t)YPAD * 256];
__device__ float    g_qn[(size_t)B_ * DM];
__device__ uint16_t g_qnhi[(size_t)B_ * DM];
__device__ float    g_sn[FEW * DM];
__device__ float    g_h1[FEW * DI];
__device__ float    g_z[FEW * DM];
__device__ float    g_sg[FEW * DM];
__device__ float    g_sm[DM];
__device__ uint16_t g_Wghi[128 * 256];
__device__ uint16_t g_WihNhi[1024 * 256];       // interleaved gate cols
__device__ uint16_t g_WsNhi[1024 * XS];         // interleaved gate cols
__device__ float    g_bias2[G1K];
__device__ float    g_A[(size_t)B_ * G1K];
__device__ uint16_t g_Xhi[(size_t)B_ * XS];
__device__ float    g_c[(size_t)B_ * 256];

// HW tanh: 1 MUFU op
__device__ __forceinline__ float htanh(float x) {
    float y;
    asm("tanh.approx.f32 %0, %1;" : "=f"(y) : "f"(x));
    return y;
}
__device__ __forceinline__ float hsig(float x) {
    return fmaf(htanh(0.5f * x), 0.5f, 0.5f);
}
__device__ __forceinline__ uint32_t pb2(float x, float y) {
    __nv_bfloat162 h = __floats2bfloat162_rn(x, y);
    return *(uint32_t*)&h;
}
__device__ __forceinline__ uint16_t pb1(float x) {
    __nv_bfloat16 h = __float2bfloat16(x);
    return *(uint16_t*)&h;
}
__device__ __forceinline__ float2 bf2x(uint32_t v) {
    return make_float2(__uint_as_float(v << 16), __uint_as_float(v & 0xffff0000u));
}
__device__ __forceinline__ uint32_t smem_u32(const void* p) {
    uint32_t a;
    asm("{ .reg .u64 t; cvta.to.shared.u64 t, %1; cvt.u32.u64 %0, t; }" : "=r"(a) : "l"(p));
    return a;
}
__device__ __forceinline__ void cpa16(uint32_t s, const void* g, int szd) {
    asm volatile("cp.async.cg.shared.global [%0], [%1], 16, %2;"
                 :: "r"(s), "l"(g), "r"(szd) : "memory");
}
#define CP_COMMIT() asm volatile("cp.async.commit_group;" ::: "memory")
#define CP_WAIT0()  asm volatile("cp.async.wait_group 0;" ::: "memory")
#define CP_WAIT1()  asm volatile("cp.async.wait_group 1;" ::: "memory")

__device__ __forceinline__ float warp_sum(float v) {
#pragma unroll
    for (int o = 16; o; o >>= 1) v += __shfl_down_sync(0xffffffffu, v, o);
    return v;
}

// ---------------- mma.sync pure-bf16 GEMM + cp.async pipeline -----------------
#define KC 32
#define SMS 40
#define BUFB 20480
#define SQ 36
#define SH 40

__device__ __forceinline__ void mma16816(float* d, const uint32_t* a,
                                         const uint32_t* b) {
    asm volatile(
        "mma.sync.aligned.m16n8k16.row.col.f32.bf16.bf16.f32 "
        "{%0,%1,%2,%3}, {%4,%5,%6,%7}, {%8,%9}, {%0,%1,%2,%3};"
        : "+f"(d[0]), "+f"(d[1]), "+f"(d[2]), "+f"(d[3])
        : "r"(a[0]), "r"(a[1]), "r"(a[2]), "r"(a[3]), "r"(b[0]), "r"(b[1]));
}

// mode 0: plain epilogue
// mode 1: C write + fused LSTM (c_old = 0)
// mode 2: fused LSTM only (gates = acc + Cadd)
// mode 3: fused hop-gate tanh mix -> g_qn/g_qnhi/g_sn (P-GEMM; grid must be (Mtiles,1))
__global__ __launch_bounds__(256, 2) void gemm_tc(
    const uint16_t* __restrict__ Ahi, int lda, int M,
    const uint16_t* __restrict__ Bhi, int ldb,
    float* __restrict__ C, int ldc,
    const float* __restrict__ Cadd, const float* __restrict__ bias,
    int NC, int mode) {
    __shared__ __align__(16) unsigned char s_raw[47104];
    float*    st_qn = (float*)s_raw;
    float*    st_c  = (float*)(s_raw + 18432);
    uint16_t* st_h  = (uint16_t*)(s_raw + 36864);

    const int t = threadIdx.x;
    const int w = t >> 5, lane = t & 31;
    const int g = lane >> 2, tig = lane & 3;
    const int m0 = blockIdx.x * 128, n0 = blockIdx.y * 128;
    const int mw = (w & 3) * 32;
    const int nw = (w >> 2) * 64;

    float acc[2][8][4];
#pragma unroll
    for (int mt = 0; mt < 2; mt++)
#pragma unroll
        for (int nt = 0; nt < 8; nt++)
#pragma unroll
            for (int e = 0; e < 4; e++) acc[mt][nt][e] = 0.f;

    const int lrow = t >> 1;
    const int lhalf = (t & 1) * 16;
    const bool mok = (m0 + lrow) < M;
    const int asz = mok ? 16 : 0;
    const size_t arow = (size_t)(m0 + lrow) * lda;
    const size_t brow = (size_t)(n0 + lrow) * ldb;
    const uint32_t sb0 = smem_u32(s_raw);
    const uint32_t soff = (uint32_t)(lrow * SMS + lhalf) * 2u;

    {
        const size_t ka = arow + lhalf;
        const size_t kb_ = brow + lhalf;
        cpa16(sb0 + soff, &Ahi[ka], asz);
        cpa16(sb0 + soff + 16, &Ahi[ka + 8], asz);
        cpa16(sb0 + 10240 + soff, &Bhi[kb_], 16);
        cpa16(sb0 + 10240 + soff + 16, &Bhi[kb_ + 8], 16);
        CP_COMMIT();
    }

    for (int c = 0; c < NC; c++) {
        if (c + 1 < NC) {
            const uint32_t sb = sb0 + (uint32_t)((c + 1) & 1) * BUFB;
            const size_t ka = arow + (c + 1) * KC + lhalf;
            const size_t kb_ = brow + (c + 1) * KC + lhalf;
            cpa16(sb + soff, &Ahi[ka], asz);
            cpa16(sb + soff + 16, &Ahi[ka + 8], asz);
            cpa16(sb + 10240 + soff, &Bhi[kb_], 16);
            cpa16(sb + 10240 + soff + 16, &Bhi[kb_ + 8], 16);
            CP_COMMIT();
            CP_WAIT1();
        } else {
            CP_WAIT0();
        }
        __syncthreads();
        const uint16_t* cA = (const uint16_t*)(s_raw + (c & 1) * BUFB);
        const uint16_t* cB = (const uint16_t*)(s_raw + (c & 1) * BUFB + 10240);
#pragma unroll
        for (int k16 = 0; k16 < 2; k16++) {
            const int kb = k16 * 16 + 2 * tig;
            uint32_t ah[2][4];
#pragma unroll
            for (int mt = 0; mt < 2; mt++) {
                int r0 = (mw + mt * 16 + g) * SMS;
                int r1 = r0 + 8 * SMS;
                ah[mt][0] = *(const uint32_t*)&cA[r0 + kb];
                ah[mt][1] = *(const uint32_t*)&cA[r1 + kb];
                ah[mt][2] = *(const uint32_t*)&cA[r0 + kb + 8];
                ah[mt][3] = *(const uint32_t*)&cA[r1 + kb + 8];
            }
#pragma unroll
            for (int nt = 0; nt < 8; nt++) {
                int rn = (nw + nt * 8 + g) * SMS;
                uint32_t bh[2];
                bh[0] = *(const uint32_t*)&cB[rn + kb];
                bh[1] = *(const uint32_t*)&cB[rn + kb + 8];
#pragma unroll
                for (int mt = 0; mt < 2; mt++) {
                    mma16816(acc[mt][nt], ah[mt], bh);
                }
            }
        }
        __syncthreads();
    }

    if (mode == 0) {
#pragma unroll
        for (int mt = 0; mt < 2; mt++) {
            int mrow0 = m0 + mw + mt * 16 + g;
#pragma unroll
            for (int half = 0; half < 2; half++) {
                int m = mrow0 + half * 8;
                if (m >= M) continue;
                size_t cro = (size_t)m * ldc;
#pragma unroll
                for (int nt = 0; nt < 8; nt++) {
                    int n = n0 + nw + nt * 8 + 2 * tig;
                    float v0 = acc[mt][nt][half * 2];
                    float v1 = acc[mt][nt][half * 2 + 1];
                    if (bias) {
                        float2 bb = *(const float2*)&bias[n];
                        v0 += bb.x; v1 += bb.y;
                    }
                    if (Cadd) {
                        float2 ca = *(const float2*)&Cadd[cro + n];
                        v0 += ca.x; v1 += ca.y;
                    }
                    *(float2*)&C[cro + n] = make_float2(v0, v1);
                }
            }
        }
    } else if (mode == 3) {
        // fused hop-gate tanh mix: rows 4k+{0,1,2,3} -> qn/sn rows k
        float* st_mix = (float*)s_raw;   // [32][264] floats = 33792 B
        const float gw0 = g_gw[0], gw1 = g_gw[1];
#pragma unroll
        for (int mt = 0; mt < 2; mt++) {
#pragma unroll
            for (int half = 0; half < 2; half++) {
                int rloc = mw + mt * 16 + g + half * 8;
#pragma unroll
                for (int nt = 0; nt < 8; nt++) {
                    int n = nw + nt * 8 + 2 * tig;
                    float v0 = acc[mt][nt][half * 2]     + bias[n];
                    float v1 = acc[mt][nt][half * 2 + 1] + bias[n + 1];
                    float t0 = htanh(v0), t1 = htanh(v1);
                    float u0 = __shfl_xor_sync(0xffffffffu, t0, 4);
                    float u1 = __shfl_xor_sync(0xffffffffu, t1, 4);
                    if ((g & 1) == 0) {
                        int gr = rloc >> 2;
                        int side = (rloc >> 1) & 1;
                        st_mix[gr * 264 + side * 128 + n]     = fmaf(gw0, t0, gw1 * u0);
                        st_mix[gr * 264 + side * 128 + n + 1] = fmaf(gw0, t1, gw1 * u1);
                    }
                }
            }
        }
        __syncthreads();
        // coalesced flush: thread -> (group, 32-col chunk)
        int gr = t >> 3, ch = t & 7;
        int ng = (m0 >> 2) + gr;
        const float* src = &st_mix[gr * 264 + ch * 32];
        if (ng < B_) {
            size_t qb = (size_t)ng * 256 + ch * 32;
#pragma unroll
            for (int i = 0; i < 8; i++)
                *(float4*)&g_qn[qb + i * 4] = *(const float4*)&src[i * 4];
#pragma unroll
            for (int i = 0; i < 4; i++) {
                uint4 pk;
                pk.x = pb2(src[i * 8 + 0], src[i * 8 + 1]);
                pk.y = pb2(src[i * 8 + 2], src[i * 8 + 3]);
                pk.z = pb2(src[i * 8 + 4], src[i * 8 + 5]);
                pk.w = pb2(src[i * 8 + 6], src[i * 8 + 7]);
                *(uint4*)&g_qnhi[qb + i * 8] = pk;
            }
        } else if (ng < B_ + FEW) {
            size_t sb_ = (size_t)(ng - B_) * 256 + ch * 32;
#pragma unroll
            for (int i = 0; i < 8; i++)
                *(float4*)&g_sn[sb_ + i * 4] = *(const float4*)&src[i * 4];
        }
    } else {
        const int pb = n0 >> 2;
        const int rr = t >> 1, sc = (t & 1) * 16;
        {
            const float* src = &g_qn[(size_t)(m0 + rr) * 256 + pb + sc];
#pragma unroll
            for (int i = 0; i < 4; i++)
                *(float4*)&st_qn[rr * SQ + sc + i * 4] = *(const float4*)&src[i * 4];
        }
        if (mode == 2) {
            const float* src = &g_c[(size_t)(m0 + rr) * 256 + pb + sc];
#pragma unroll
            for (int i = 0; i < 4; i++)
                *(float4*)&st_c[rr * SQ + sc + i * 4] = *(const float4*)&src[i * 4];
        }
        __syncthreads();
#pragma unroll
        for (int mt = 0; mt < 2; mt++) {
#pragma unroll
            for (int half = 0; half < 2; half++) {
                int mloc = mw + mt * 16 + g + half * 8;
                size_t cro = (size_t)(m0 + mloc) * ldc;
#pragma unroll
                for (int nt = 0; nt < 8; nt++) {
                    int n = n0 + nw + nt * 8 + 2 * tig;
                    float v0 = acc[mt][nt][half * 2];
                    float v1 = acc[mt][nt][half * 2 + 1];
                    if (mode == 1) {
                        float2 bb = *(const float2*)&bias[n];
                        v0 += bb.x; v1 += bb.y;
                        *(float2*)&C[cro + n] = make_float2(v0, v1);
                    } else {
                        float2 ca = *(const float2*)&Cadd[cro + n];
                        v0 += ca.x; v1 += ca.y;
                    }
                    float u0 = __shfl_xor_sync(0xffffffffu, v0, 1);
                    float u1 = __shfl_xor_sync(0xffffffffu, v1, 1);
                    if ((tig & 1) == 0) {
                        int ploc = (nw >> 2) + nt * 2 + (tig >> 1);
                        float cold = (mode == 1) ? 0.f : st_c[mloc * SQ + ploc];
                        float cn = hsig(v1) * cold + hsig(v0) * htanh(u0);
                        float hv = st_qn[mloc * SQ + ploc] + hsig(u1) * htanh(cn);
                        st_c[mloc * SQ + ploc] = cn;
                        st_h[mloc * SH + ploc] = pb1(hv);
                    }
                }
            }
        }
        __syncthreads();
        {
#pragma unroll
            for (int i = 0; i < 4; i++)
                *(float4*)&g_c[(size_t)(m0 + rr) * 256 + pb + sc + i * 4] =
                    *(const float4*)&st_c[rr * SQ + sc + i * 4];
            uint16_t* dst = &g_Xhi[(size_t)(m0 + rr) * XS + pb + sc];
#pragma unroll
            for (int i = 0; i < 2; i++)
                *(uint4*)&dst[i * 8] = *(const uint4*)&st_h[rr * SH + sc + i * 8];
        }
    }
}

// ---------------- merged prep (R14 version) -------------------------------------
__global__ void k_prep(const float* __restrict__ gcn_w, const float* __restrict__ gcn_wb,
                       const float* __restrict__ gcn_b, const float* __restrict__ hop_gate,
                       const float* __restrict__ attn_w,
                       const float* __restrict__ w_ih, const float* __restrict__ w_hh,
                       const float* __restrict__ b_ih, const float* __restrict__ b_hh) {
    int t = threadIdx.x;  // 256
    int b = blockIdx.x;   // 1153
    if (b == 0) {
        if (t == 0) {
            float a = hop_gate[0], bb = hop_gate[1];
            float m = fmaxf(a, bb);
            float ea = expf(a - m), eb = expf(bb - m);
            g_gw[0] = ea / (ea + eb);
            g_gw[1] = eb / (ea + eb);
        }
        if (t < 128) {
            g_biasvec[t] = gcn_wb[t] + gcn_b[t];
            float ur = 0.f, ue = 0.f;
            for (int d = 0; d < 128; d++) {
                float aw = attn_w[d];
                ur += gcn_w[d * 256 + t] * aw;
                ue += gcn_w[d * 256 + 128 + t] * aw;
            }
            g_u[t] = ur;
            g_u[128 + t] = ue;
        }
    } else if (b <= 128) {
        int n = b - 1;
        g_Wghi[n * 256 + t] = pb1(gcn_w[n * 256 + t]);
    } else {
        int n = b - 129;  // interleaved gate col: src = (n&3)*512 + (n>>2)
        int src = (n & 3) * 512 + (n >> 2);
        g_WihNhi[n * 256 + t] = pb1(w_ih[src * 256 + t]);
        g_WsNhi[n * XS + t]   = pb1(w_hh[src * 512 + t]);
        if (t < (XS - 261)) g_WsNhi[n * XS + 261 + t] = 0;
        if (t == 0) g_bias2[n] = b_ih[src] + b_hh[src];
    }
}

// ---------------- per-symbol score scalars + fp16 table (2 symbols/warp) -------
__global__ __launch_bounds__(256) void k_scal(const float* __restrict__ emb) {
    __shared__ float su[256];
    int t = threadIdx.x;
    su[t] = g_u[t];
    __syncthreads();
    int warp = t >> 5, lane = t & 31;
    int s0 = (blockIdx.x * 8 + warp) * 2;
    float4 e0 = *(const float4*)&emb[(size_t)s0 * 128 + lane * 4];
    float4 e1 = *(const float4*)&emb[(size_t)(s0 + 1) * 128 + lane * 4];
    float4 ur = ((const float4*)su)[lane];
    float4 ue = ((const float4*)(su + 128))[lane];
    float pr0 = e0.x * ur.x + e0.y * ur.y + e0.z * ur.z + e0.w * ur.w;
    float pe0 = e0.x * ue.x + e0.y * ue.y + e0.z * ue.z + e0.w * ue.w;
    float pr1 = e1.x * ur.x + e1.y * ur.y + e1.z * ur.z + e1.w * ur.w;
    float pe1 = e1.x * ue.x + e1.y * ue.y + e1.z * ue.z + e1.w * ue.w;
#pragma unroll
    for (int o = 16; o; o >>= 1) {
        pr0 += __shfl_xor_sync(0xffffffffu, pr0, o);
        pe0 += __shfl_xor_sync(0xffffffffu, pe0, o);
        pr1 += __shfl_xor_sync(0xffffffffu, pr1, o);
        pe1 += __shfl_xor_sync(0xffffffffu, pe1, o);
    }
    if (lane == 0) {
        g_scal[s0] = make_float4(pr0, pe0, 0.f, 0.f);
        g_scal[s0 + 1] = make_float4(pr1, pe1, 0.f, 0.f);
    }
    __half2 h0 = __float22half2_rn(make_float2(e0.x, e0.y));
    __half2 h1 = __float22half2_rn(make_float2(e0.z, e0.w));
    uint2 pk;
    pk.x = *(uint32_t*)&h0;
    pk.y = *(uint32_t*)&h1;
    ((uint2*)g_embh)[(size_t)s0 * 32 + lane] = pk;
    h0 = __float22half2_rn(make_float2(e1.x, e1.y));
    h1 = __float22half2_rn(make_float2(e1.z, e1.w));
    pk.x = *(uint32_t*)&h0;
    pk.y = *(uint32_t*)&h1;
    ((uint2*)g_embh)[(size_t)(s0 + 1) * 32 + lane] = pk;
}

// ---------------- neighbor encoder: queries + support in ONE launch ------------
__global__ __launch_bounds__(512) void k_neigh(
    const int* __restrict__ q0, const int* __restrict__ q1,
    const int* __restrict__ q2, const int* __restrict__ q3,
    const int* __restrict__ s0p, const int* __restrict__ s1p,
    const int* __restrict__ s2p, const int* __restrict__ s3p) {
    __shared__ int4 smeta[16][64];
    const int t = threadIdx.x;
    const int w = t >> 5, lane = t & 31;
    const int g = w & 3;
    const bool is_sup = blockIdx.x >= (B_ / 4);
    int nb, rowbase;
    const int *c0, *c1, *c2, *c3;
    if (!is_sup) {
        nb = blockIdx.x * 4 + (w >> 2);
        rowbase = 0;
        c0 = q0; c1 = q1; c2 = q2; c3 = q3;
    } else {
        nb = (blockIdx.x - B_ / 4) * 4 + (w >> 2);
        if (nb >= FEW) return;
        rowbase = B_ * 4;
        c0 = s0p; c1 = s1p; c2 = s2p; c3 = s3p;
    }
    const int* cp = (g == 0) ? c0 : (g == 1) ? c1 : (g == 2) ? c2 : c3;

    int2 p0 = ((const int2*)cp)[(size_t)nb * NN_ + lane];
    int2 p1 = ((const int2*)cp)[(size_t)nb * NN_ + 32 + lane];
    float4 s0r = g_scal[p0.x], s0e = g_scal[p0.y];
    float4 s1r = g_scal[p1.x], s1e = g_scal[p1.y];
    float e0 = s0r.x + s0e.y;
    float e1 = s1r.x + s1e.y;
    float m = fmaxf(e0, e1);
#pragma unroll
    for (int o = 16; o; o >>= 1) m = fmaxf(m, __shfl_xor_sync(0xffffffffu, m, o));
    float w0 = __expf(e0 - m), w1 = __expf(e1 - m);
    float s = w0 + w1;
#pragma unroll
    for (int o = 16; o; o >>= 1) s += __shfl_xor_sync(0xffffffffu, s, o);
    float inv = __fdividef(1.f, s);

    smeta[w][lane]      = make_int4(p0.x, p0.y, __float_as_int(w0), 0);
    smeta[w][lane + 32] = make_int4(p1.x, p1.y, __float_as_int(w1), 0);
    __syncwarp();

    const uint2* e2 = (const uint2*)g_embh;
    float4 accR = make_float4(0.f, 0.f, 0.f, 0.f);
    float4 accE = make_float4(0.f, 0.f, 0.f, 0.f);
#pragma unroll 4
    for (int j = 0; j < NN_; j++) {
        int4 mt = smeta[w][j];
        float wj = __int_as_float(mt.z);
        uint2 vr = __ldg(&e2[(size_t)mt.x * 32 + lane]);
        uint2 ve = __ldg(&e2[(size_t)mt.y * 32 + lane]);
        float2 r01 = __half22float2(*(__half2*)&vr.x);
        float2 r23 = __half22float2(*(__half2*)&vr.y);
        float2 q01 = __half22float2(*(__half2*)&ve.x);
        float2 q23 = __half22float2(*(__half2*)&ve.y);
        accR.x += wj * r01.x; accR.y += wj * r01.y;
        accR.z += wj * r23.x; accR.w += wj * r23.y;
        accE.x += wj * q01.x; accE.y += wj * q01.y;
        accE.z += wj * q23.x; accE.w += wj * q23.y;
    }
    accR.x *= inv; accR.y *= inv; accR.z *= inv; accR.w *= inv;
    accE.x *= inv; accE.y *= inv; accE.z *= inv; accE.w *= inv;

    size_t yrow = (size_t)(rowbase + nb * 4 + g) * 256;
    *(uint2*)&g_Yhi[yrow + 4 * lane] =
        make_uint2(pb2(accR.x, accR.y), pb2(accR.z, accR.w));
    *(uint2*)&g_Yhi[yrow + 128 + 4 * lane] =
        make_uint2(pb2(accE.x, accE.y), pb2(accE.z, accE.w));
}

// ---------------- support encoder chain (separate, parallel kernels) -----------
__global__ void k_sup1(const float* __restrict__ p1_w, const float* __restrict__ p1_b) {
    int warp = threadIdx.x >> 5, lane = threadIdx.x & 31;
    int gw = blockIdx.x * 8 + warp;
    if (gw >= FEW * DI) return;
    int f = gw / DI, j = gw - f * DI;
    float s = 0.f;
#pragma unroll
    for (int i = 0; i < 8; i++) {
        int k = lane + i * 32;
        s += g_sn[f * DM + k] * p1_w[j * DM + k];
    }
    s = warp_sum(s);
    if (lane == 0) g_h1[f * DI + j] = fmaxf(s + p1_b[j], 0.f);
}

__global__ void k_sup2(const float* __restrict__ p2_w, const float* __restrict__ p2_b) {
    int warp = threadIdx.x >> 5, lane = threadIdx.x & 31;
    int gw = blockIdx.x * 8 + warp;
    if (gw >= FEW * DM) return;
    int f = gw / DM, d = gw - f * DM;
    float s = 0.f;
#pragma unroll
    for (int i = 0; i < 16; i++) {
        int k = lane + i * 32;
        s += g_h1[f * DI + k] * p2_w[d * DI + k];
    }
    s = warp_sum(s);
    if (lane == 0) g_z[f * DM + d] = s + p2_b[d] + g_sn[f * DM + d];
}

__global__ void k_lnmean(const float* __restrict__ ln_g, const float* __restrict__ ln_b) {
    __shared__ float sred[8];
    int t = threadIdx.x;
    int lane = t & 31, warp = t >> 5;
    float gg = ln_g[t], bb = ln_b[t];
    float msum = 0.f;
    for (int f = 0; f < FEW; f++) {
        float z = g_z[f * DM + t];
        float v = warp_sum(z);
        if (lane == 0) sred[warp] = v;
        __syncthreads();
        if (t == 0) {
            float s = 0.f;
            for (int w = 0; w < 8; w++) s += sred[w];
            sred[0] = s * (1.f / 256.f);
        }
        __syncthreads();
        float mu = sred[0];
        __syncthreads();
        float dv = z - mu;
        float v2 = warp_sum(dv * dv);
        if (lane == 0) sred[warp] = v2;
        __syncthreads();
        if (t == 0) {
            float s = 0.f;
            for (int w = 0; w < 8; w++) s += sred[w];
            sred[0] = s * (1.f / 256.f);
        }
        __syncthreads();
        float var = sred[0];
        __syncthreads();
        float o = dv * rsqrtf(var + 1e-6f) * gg + bb;
        g_sg[f * DM + t] = o;
        msum += o;
    }
    g_sm[t] = msum * (1.f / (float)FEW);
}

__global__ void k_sgw(const float* __restrict__ w_hh) {
    int warp = threadIdx.x >> 5, lane = threadIdx.x & 31;
    int gw = blockIdx.x * 8 + warp;
    if (gw >= FEW * G1K) return;
    int f = gw / G1K, n = gw - f * G1K;
    int src = (n & 3) * 512 + (n >> 2);   // interleaved gate col
    float s = 0.f;
#pragma unroll
    for (int i = 0; i < 8; i++) {
        int k = lane + i * 32;
        s += g_sg[f * DM + k] * w_hh[src * 512 + 256 + k];
    }
    s = warp_sum(s);
    if (lane == 0) g_WsNhi[n * XS + 256 + f] = pb1(s);
}

// ---------------- attention softmax over support (per LSTM step) ---------------
__global__ __launch_bounds__(256) void k_attn() {
    __shared__ float ssg[FEW * 256];
    int t = threadIdx.x;
    for (int i = t; i < FEW * 256; i += 256) ssg[i] = g_sg[i];
    __syncthreads();
    int w = t >> 5, lane = t & 31;
    size_t row = (size_t)blockIdx.x * 8 + w;
    uint4 h4 = *(const uint4*)&g_Xhi[row * XS + lane * 8];
    float hv[8];
    {
        float2 a;
        a = bf2x(h4.x); hv[0] = a.x; hv[1] = a.y;
        a = bf2x(h4.y); hv[2] = a.x; hv[3] = a.y;
        a = bf2x(h4.z); hv[4] = a.x; hv[5] = a.y;
        a = bf2x(h4.w); hv[6] = a.x; hv[7] = a.y;
    }
    float s[FEW];
#pragma unroll
    for (int f = 0; f < FEW; f++) {
        float acc = 0.f;
#pragma unroll
        for (int k = 0; k < 8; k++) acc += hv[k] * ssg[f * 256 + lane * 8 + k];
#pragma unroll
        for (int o = 16; o; o >>= 1) acc += __shfl_xor_sync(0xffffffffu, acc, o);
        s[f] = acc;
    }
    float m = s[0];
#pragma unroll
    for (int f = 1; f < FEW; f++) m = fmaxf(m, s[f]);
    float sum = 0.f, e[FEW];
#pragma unroll
    for (int f = 0; f < FEW; f++) { e[f] = __expf(s[f] - m); sum += e[f]; }
    float inv = __fdividef(1.f, sum);
    if (lane < FEW) {
        g_Xhi[row * XS + 256 + lane] = pb1(e[lane] * inv);
    } else {
        g_Xhi[row * XS + 261 + (lane - FEW)] = 0;
    }
}

// ---------------- final output dot ---------------------------------------------
__global__ __launch_bounds__(256) void k_final(float* __restrict__ out) {
    __shared__ float ssm[256];
    int t = threadIdx.x;
    ssm[t] = g_sm[t];
    __syncthreads();
    int w = t >> 5, lane = t & 31;
    size_t row = (size_t)blockIdx.x * 8 + w;
    uint4 h4 = *(const uint4*)&g_Xhi[row * XS + lane * 8];
    float acc = 0.f;
    {
        float2 a;
        const float* sm = &ssm[lane * 8];
        a = bf2x(h4.x); acc += a.x * sm[0] + a.y * sm[1];
        a = bf2x(h4.y); acc += a.x * sm[2] + a.y * sm[3];
        a = bf2x(h4.z); acc += a.x * sm[4] + a.y * sm[5];
        a = bf2x(h4.w); acc += a.x * sm[6] + a.y * sm[7];
    }
#pragma unroll
    for (int o = 16; o; o >>= 1) acc += __shfl_xor_sync(0xffffffffu, acc, o);
    if (lane == 0) out[row] = acc;
}

// ---------------- host launcher ------------------------------------------------
template <typename T>
static float* symaddrf(T& sym) {
    void* p = nullptr;
    cudaGetSymbolAddress(&p, sym);
    return (float*)p;
}
template <typename T>
static uint16_t* symaddru(T& sym) {
    void* p = nullptr;
    cudaGetSymbolAddress(&p, sym);
    return (uint16_t*)p;
}

extern "C" void kernel_launch(void* const* d_in, const int* in_sizes, int n_in,
                              void* d_out, int out_size) {
    const int* q_l1 = (const int*)d_in[0];
    const int* q_l2 = (const int*)d_in[1];
    const int* q_r1 = (const int*)d_in[2];
    const int* q_r2 = (const int*)d_in[3];
    const int* s_l1 = (const int*)d_in[4];
    const int* s_l2 = (const int*)d_in[5];
    const int* s_r1 = (const int*)d_in[6];
    const int* s_r2 = (const int*)d_in[7];
    const float* emb      = (const float*)d_in[12];
    const float* gcn_w    = (const float*)d_in[13];
    const float* gcn_wb   = (const float*)d_in[14];
    const float* gcn_b    = (const float*)d_in[15];
    const float* hop_gate = (const float*)d_in[16];
    const float* attn_w   = (const float*)d_in[17];
    const float* p1_w = (const float*)d_in[19];
    const float* p1_b = (const float*)d_in[20];
    const float* p2_w = (const float*)d_in[21];
    const float* p2_b = (const float*)d_in[22];
    const float* ln_g = (const float*)d_in[23];
    const float* ln_b = (const float*)d_in[24];
    const float* w_ih = (const float*)d_in[25];
    const float* w_hh = (const float*)d_in[26];
    const float* b_ih = (const float*)d_in[27];
    const float* b_hh = (const float*)d_in[28];
    float* out = (float*)d_out;

    uint16_t* pYhi   = symaddru(g_Yhi);
    uint16_t* pWghi  = symaddru(g_Wghi);
    uint16_t* pWihhi = symaddru(g_WihNhi);
    uint16_t* pWshi  = symaddru(g_WsNhi);
    uint16_t* pQhi   = symaddru(g_qnhi);
    uint16_t* pXhi   = symaddru(g_Xhi);
    float* pBias2 = symaddrf(g_bias2);
    float* pBiasV = symaddrf(g_biasvec);
    float* pA     = symaddrf(g_A);

    // prep (merged, R14 version)
    k_prep<<<1153, 256>>>(gcn_w, gcn_wb, gcn_b, hop_gate, attn_w,
                          w_ih, w_hh, b_ih, b_hh);
    k_scal<<<NSYM / 16, 256>>>(emb);

    // neighbor encoders: queries + support in one launch
    k_neigh<<<B_ / 4 + 2, 512>>>(q_l1, q_l2, q_r1, q_r2,
                                 s_l1, s_l2, s_r1, s_r2);

    // P-GEMM with fused tanh/hop-gate mix epilogue (mode 3)
    gemm_tc<<<dim3((YROWS + 127) / 128, 1), 256>>>(
        pYhi, 256, YROWS, pWghi, 256, nullptr, 0, nullptr, pBiasV, 8, 3);

    // support encoder (parallel, coalesced)
    k_sup1<<<(FEW * DI) / 8, 256>>>(p1_w, p1_b);
    k_sup2<<<(FEW * DM) / 8, 256>>>(p2_w, p2_b);
    k_lnmean<<<1, 256>>>(ln_g, ln_b);
    k_sgw<<<(FEW * G1K + 7) / 8, 256>>>(w_hh);

    // A-GEMM (mode 1): fused step-1 LSTM cell
    gemm_tc<<<dim3(B_ / 128, G1K / 128), 256>>>(
        pQhi, 256, B_, pWihhi, 256, pA, G1K, nullptr, pBias2, 8, 1);
    k_attn<<<B_ / 8, 256>>>();

    // steps 2..4: gates = A + X @ WsN^T, fused cell (mode 2)
    for (int s = 2; s <= 4; s++) {
        gemm_tc<<<dim3(B_ / 128, G1K / 128), 256>>>(
            pXhi, XS, B_, pWshi, XS, nullptr, G1K, pA, nullptr, 9, 2);
        if (s < 4)
            k_attn<<<B_ / 8, 256>>>();
        else
            k_final<<<B_ / 8, 256>>>(out);
    }
}